// round 16
// baseline (speedup 1.0000x reference)
#include <cuda_runtime.h>
#include <cuda_fp16.h>
#include <cstdint>

#define N_NODES 50000
#define N_EDGES 800000
#define EE (N_EDGES + N_NODES)   // edges + self loops = 850000
#define NG 64
#define NCLS 10
#define NEG_SLOPE 0.2f
#define EPS 1e-16f
#define NB_SCAN ((N_NODES + 255) / 256)

// ---------------- scratch (static device globals; no runtime alloc) -------------
__device__ __align__(16) float  g_bufB[N_NODES * 256];  // gat output / next gemm input
__device__ __align__(16) __half g_h16[N_NODES * 256];   // fp16 h (written by gemm epilogue)
__device__ __align__(16) float  g_as1[N_NODES * 4];
__device__ __align__(16) float  g_ad1[N_NODES * 4];
__device__ __align__(16) float  g_as2[N_NODES * 4];
__device__ __align__(16) float  g_ad2[N_NODES * 4];
__device__ __align__(16) float  g_as3[N_NODES];
__device__ __align__(16) float  g_ad3[N_NODES];
__device__ __align__(16) int    g_batch[N_NODES];
__device__ __align__(16) int    g_deg[N_NODES];
__device__ __align__(16) int    g_incl[N_NODES];
__device__ __align__(16) int    g_bsum[256];
__device__ __align__(16) int    g_off[N_NODES + 1];
__device__ __align__(16) int    g_cursor[N_NODES];
__device__ __align__(16) int    g_csr_src[EE];
__device__ __align__(16) float  g_pool[NG * 64 + NG];

// ---------------- helpers -------------------------------------------------------
__device__ __forceinline__ void red_add_v2(float* addr, float a, float b) {
    asm volatile("red.global.add.v2.f32 [%0], {%1,%2};"
                 :: "l"(addr), "f"(a), "f"(b) : "memory");
}
__device__ __forceinline__ float lrelu(float v) { return v >= 0.0f ? v : NEG_SLOPE * v; }

__device__ __forceinline__ float f2tf32(float x) {
    uint32_t r;
    asm("cvt.rna.tf32.f32 %0, %1;" : "=r"(r) : "f"(x));
    return __uint_as_float(r);
}

__device__ __forceinline__ void mma_tf32(float* d, uint32_t a0, uint32_t a1,
                                         uint32_t a2, uint32_t a3,
                                         uint32_t b0, uint32_t b1) {
    asm("mma.sync.aligned.m16n8k8.row.col.f32.tf32.tf32.f32 "
        "{%0,%1,%2,%3},{%4,%5,%6,%7},{%8,%9},{%0,%1,%2,%3};"
        : "+f"(d[0]), "+f"(d[1]), "+f"(d[2]), "+f"(d[3])
        : "r"(a0), "r"(a1), "r"(a2), "r"(a3), "r"(b0), "r"(b1));
}

__device__ __forceinline__ uint32_t pack_h2(float a, float b) {
    __half2 h = __floats2half2_rn(a, b);
    return *(uint32_t*)&h;
}
__device__ __forceinline__ float2 unpack_h2(uint32_t u) {
    return __half22float2(*(__half2*)&u);
}

// edge-index dtype detect (shared-per-block). JAX may hand us int32 despite the
// reference requesting int64; fused ints read as int64 are wildly out of range.
__device__ __forceinline__ int detect_ei(const void* ei) {
    const long long* e64 = (const long long*)ei;
    int ok = 1;
    for (int j = 0; j < 8; j++) {
        long long v = e64[j];
        if (v < 0 || v >= N_NODES) ok = 0;
    }
    return ok;
}

// ---------------- zero_all: deg + pool + all as/ad buffers ----------------------
__global__ void zero_all(int* __restrict__ deg, float* __restrict__ pool,
                         float* __restrict__ as1, float* __restrict__ ad1,
                         float* __restrict__ as2, float* __restrict__ ad2,
                         float* __restrict__ as3, float* __restrict__ ad3) {
    int i = blockIdx.x * blockDim.x + threadIdx.x;
    if (i < N_NODES * 4) { as1[i] = 0.f; ad1[i] = 0.f; as2[i] = 0.f; ad2[i] = 0.f; }
    if (i < N_NODES)     { as3[i] = 0.f; ad3[i] = 0.f; deg[i] = 0; }
    if (i < NG * 64 + NG) pool[i] = 0.f;
}

// ---------------- prep2: dtype detect + degree hist + batch convert -------------
__global__ void prep2(const void* ei, const void* bat, int* __restrict__ deg,
                      int* __restrict__ batch) {
    __shared__ int f_e, f_b;
    if (threadIdx.x == 0) {
        f_e = detect_ei(ei);
        const long long* b64 = (const long long*)bat;
        int okb = 1;
        for (int j = 0; j < 8; j++) {
            long long v = b64[N_NODES / 2 - 1 - j];
            if (v < 0 || v >= NG) okb = 0;
        }
        f_b = okb;
    }
    __syncthreads();
    int i = blockIdx.x * blockDim.x + threadIdx.x;
    if (i < EE) {
        int d;
        if (i < N_EDGES) {
            if (f_e) d = (int)((const long long*)ei)[N_EDGES + i];
            else     d = ((const int*)ei)[N_EDGES + i];
        } else {
            d = i - N_EDGES;
        }
        atomicAdd(&deg[d], 1);
    }
    if (i < N_NODES) {
        if (f_b) batch[i] = (int)((const long long*)bat)[i];
        else     batch[i] = ((const int*)bat)[i];
    }
}

// ---------------- CSR scan (multi-block) ----------------------------------------
__global__ void scan1(const int* __restrict__ deg, int* __restrict__ incl,
                      int* __restrict__ bsum) {
    __shared__ int s[256];
    int t = threadIdx.x;
    int i = blockIdx.x * 256 + t;
    int v = (i < N_NODES) ? deg[i] : 0;
    s[t] = v;
    __syncthreads();
#pragma unroll
    for (int o = 1; o < 256; o <<= 1) {
        int x = (t >= o) ? s[t - o] : 0;
        __syncthreads();
        s[t] += x;
        __syncthreads();
    }
    if (i < N_NODES) incl[i] = s[t];
    if (t == 255) bsum[blockIdx.x] = s[255];
}

__global__ void scan2(int* __restrict__ bsum) {
    __shared__ int s[256];
    int t = threadIdx.x;
    int v = (t < NB_SCAN) ? bsum[t] : 0;
    s[t] = v;
    __syncthreads();
#pragma unroll
    for (int o = 1; o < 256; o <<= 1) {
        int x = (t >= o) ? s[t - o] : 0;
        __syncthreads();
        s[t] += x;
        __syncthreads();
    }
    bsum[t] = s[t] - v;
}

__global__ void scan3(const int* __restrict__ deg, const int* __restrict__ incl,
                      const int* __restrict__ bsum, int* __restrict__ off,
                      int* __restrict__ cursor) {
    int i = blockIdx.x * blockDim.x + threadIdx.x;
    if (i >= N_NODES) return;
    int o = incl[i] - deg[i] + bsum[i >> 8];
    off[i] = o;
    cursor[i] = o;
    if (i == 0) off[N_NODES] = EE;
}

// scatter reads edge_index directly (no src/dst intermediates)
__global__ void scatter_csr(const void* ei, int* __restrict__ cursor,
                            int* __restrict__ csr_src) {
    __shared__ int f_e;
    if (threadIdx.x == 0) f_e = detect_ei(ei);
    __syncthreads();
    int i = blockIdx.x * blockDim.x + threadIdx.x;
    if (i >= EE) return;
    int s, d;
    if (i < N_EDGES) {
        if (f_e) {
            const long long* e = (const long long*)ei;
            s = (int)e[i];
            d = (int)e[N_EDGES + i];
        } else {
            const int* e = (const int*)ei;
            s = e[i];
            d = e[N_EDGES + i];
        }
    } else {
        s = d = i - N_EDGES;
    }
    int pos = atomicAdd(&cursor[d], 1);
    csr_src[pos] = s;
}

// ---------------- TF32 GEMM (BK=32) with fused dots + fp16 emit epilogue ---------
// BK=32 halves barrier count vs BK=16; loads go straight LDG->cvt->STS (register
// prefetch was measured neutral, so occupancy-based overlap covers latency).
template <int BN>
__global__ void __launch_bounds__(256)
mma_gemm_fused(const float* __restrict__ A, const float* __restrict__ Bm,
               const float* __restrict__ a_src, const float* __restrict__ a_dst,
               float* __restrict__ as, float* __restrict__ ad,
               __half* __restrict__ h16, int M, int N, int K) {
    constexpr int WN = BN / 4;
    constexpr int NT = WN / 8;
    constexpr int NBL = (BN == 128) ? 4 : 2;   // B-tile float4 loads per thread
    __shared__ float As[32][136];
    __shared__ float Bs[32][BN + 8];
    int tid = threadIdx.x;
    int lane = tid & 31, warp = tid >> 5;
    int wm = (warp & 1) * 64, wn = (warp >> 1) * WN;
    int m0 = blockIdx.y * 128, n0 = blockIdx.x * BN;
    int l3 = lane & 3, l2 = lane >> 2;

    float acc[4][NT][4] = {};

    for (int k0 = 0; k0 < K; k0 += 32) {
        // A tile 128x32 -> As[k][m] transposed (4 float4 per thread)
#pragma unroll
        for (int i = 0; i < 4; i++) {
            int f = tid * 4 + i;
            int row = f >> 3, c4 = (f & 7) << 2;
            float4 av = make_float4(0.f, 0.f, 0.f, 0.f);
            if (m0 + row < M)
                av = *(const float4*)(A + (size_t)(m0 + row) * K + k0 + c4);
            As[c4 + 0][row] = f2tf32(av.x);
            As[c4 + 1][row] = f2tf32(av.y);
            As[c4 + 2][row] = f2tf32(av.z);
            As[c4 + 3][row] = f2tf32(av.w);
        }
        // B tile 32xBN
        if (BN == 128) {
#pragma unroll
            for (int i = 0; i < 4; i++) {
                int f = tid * 4 + i;
                int row = f >> 5, c4 = (f & 31) << 2;
                float4 bv = *(const float4*)(Bm + (size_t)(k0 + row) * N + n0 + c4);
                Bs[row][c4 + 0] = f2tf32(bv.x);
                Bs[row][c4 + 1] = f2tf32(bv.y);
                Bs[row][c4 + 2] = f2tf32(bv.z);
                Bs[row][c4 + 3] = f2tf32(bv.w);
            }
        } else {
#pragma unroll
            for (int i = 0; i < 2; i++) {
                int f = tid * 2 + i;
                int row = f >> 4, c4 = (f & 15) << 2;
                float4 bv = *(const float4*)(Bm + (size_t)(k0 + row) * N + n0 + c4);
                Bs[row][c4 + 0] = f2tf32(bv.x);
                Bs[row][c4 + 1] = f2tf32(bv.y);
                Bs[row][c4 + 2] = f2tf32(bv.z);
                Bs[row][c4 + 3] = f2tf32(bv.w);
            }
        }
        __syncthreads();

#pragma unroll
        for (int kk = 0; kk < 32; kk += 8) {
            uint32_t bf[NT][2];
#pragma unroll
            for (int j = 0; j < NT; j++) {
                bf[j][0] = __float_as_uint(Bs[kk + l3][wn + j * 8 + l2]);
                bf[j][1] = __float_as_uint(Bs[kk + l3 + 4][wn + j * 8 + l2]);
            }
#pragma unroll
            for (int i = 0; i < 4; i++) {
                uint32_t a0 = __float_as_uint(As[kk + l3][wm + i * 16 + l2]);
                uint32_t a1 = __float_as_uint(As[kk + l3][wm + i * 16 + l2 + 8]);
                uint32_t a2 = __float_as_uint(As[kk + l3 + 4][wm + i * 16 + l2]);
                uint32_t a3 = __float_as_uint(As[kk + l3 + 4][wm + i * 16 + l2 + 8]);
#pragma unroll
                for (int j = 0; j < NT; j++)
                    mma_tf32(acc[i][j], a0, a1, a2, a3, bf[j][0], bf[j][1]);
            }
        }
        __syncthreads();
    }

    // ---- fused epilogue: h16 emit + per-head attention dot partials ----
    int H = N >> 6;
    int head = (n0 + wn) >> 6;
    float asv[2 * NT], adv[2 * NT];
#pragma unroll
    for (int j = 0; j < NT; j++) {
        int cc = (n0 + wn + j * 8 + 2 * l3) & 63;
        asv[2 * j]     = a_src[head * 64 + cc];
        asv[2 * j + 1] = a_src[head * 64 + cc + 1];
        adv[2 * j]     = a_dst[head * 64 + cc];
        adv[2 * j + 1] = a_dst[head * 64 + cc + 1];
    }
#pragma unroll
    for (int i = 0; i < 4; i++) {
        int r0 = m0 + wm + i * 16 + l2;
        int r1 = r0 + 8;
        float ps0 = 0.f, pd0 = 0.f, ps1 = 0.f, pd1 = 0.f;
#pragma unroll
        for (int j = 0; j < NT; j++) {
            int c = n0 + wn + j * 8 + 2 * l3;
            ps0 += acc[i][j][0] * asv[2 * j] + acc[i][j][1] * asv[2 * j + 1];
            pd0 += acc[i][j][0] * adv[2 * j] + acc[i][j][1] * adv[2 * j + 1];
            ps1 += acc[i][j][2] * asv[2 * j] + acc[i][j][3] * asv[2 * j + 1];
            pd1 += acc[i][j][2] * adv[2 * j] + acc[i][j][3] * adv[2 * j + 1];
            if (r0 < M)
                ((uint32_t*)(h16 + (size_t)r0 * N))[c >> 1] = pack_h2(acc[i][j][0], acc[i][j][1]);
            if (r1 < M)
                ((uint32_t*)(h16 + (size_t)r1 * N))[c >> 1] = pack_h2(acc[i][j][2], acc[i][j][3]);
        }
        ps0 += __shfl_xor_sync(0xffffffffu, ps0, 1);
        ps0 += __shfl_xor_sync(0xffffffffu, ps0, 2);
        pd0 += __shfl_xor_sync(0xffffffffu, pd0, 1);
        pd0 += __shfl_xor_sync(0xffffffffu, pd0, 2);
        ps1 += __shfl_xor_sync(0xffffffffu, ps1, 1);
        ps1 += __shfl_xor_sync(0xffffffffu, ps1, 2);
        pd1 += __shfl_xor_sync(0xffffffffu, pd1, 1);
        pd1 += __shfl_xor_sync(0xffffffffu, pd1, 2);
        if (l3 == 0) {
            if (r0 < M) {
                atomicAdd(&as[r0 * H + head], ps0);
                atomicAdd(&ad[r0 * H + head], pd0);
            }
            if (r1 < M) {
                atomicAdd(&as[r1 * H + head], ps1);
                atomicAdd(&ad[r1 * H + head], pd1);
            }
        }
    }
}

// ---------------- fused GAT layer (softmax + aggregate + bias + relu) -----------
// Max-subtraction removed (softmax shift-invariant; e is O(+-1), no overflow).
__global__ void gat_node4(const __half* __restrict__ h16, const float* __restrict__ as,
                          const float* __restrict__ ad, const int* __restrict__ off,
                          const int* __restrict__ csr_src,
                          const float* __restrict__ bias, float* __restrict__ out) {
    int node = (blockIdx.x * blockDim.x + threadIdx.x) >> 5;
    int lane = threadIdx.x & 31;
    if (node >= N_NODES) return;
    int start = off[node], end = off[node + 1];
    float4 adv = ((const float4*)ad)[node];

    int head = lane >> 3;
    float advh = head == 0 ? adv.x : head == 1 ? adv.y : head == 2 ? adv.z : adv.w;
    float acc[8] = {};
    float den = 0.0f;
    int k = start;
    for (; k + 2 <= end; k += 2) {
        int s0 = __ldg(&csr_src[k]);
        int s1 = __ldg(&csr_src[k + 1]);
        float as0 = __ldg(&as[s0 * 4 + head]);
        float as1 = __ldg(&as[s1 * 4 + head]);
        uint4 u = ((const uint4*)(h16 + (size_t)s0 * 256))[lane];
        uint4 w = ((const uint4*)(h16 + (size_t)s1 * 256))[lane];
        float ex0 = __expf(lrelu(as0 + advh));
        float ex1 = __expf(lrelu(as1 + advh));
        den += ex0 + ex1;
        float2 f;
        f = unpack_h2(u.x); acc[0] += f.x * ex0; acc[1] += f.y * ex0;
        f = unpack_h2(u.y); acc[2] += f.x * ex0; acc[3] += f.y * ex0;
        f = unpack_h2(u.z); acc[4] += f.x * ex0; acc[5] += f.y * ex0;
        f = unpack_h2(u.w); acc[6] += f.x * ex0; acc[7] += f.y * ex0;
        f = unpack_h2(w.x); acc[0] += f.x * ex1; acc[1] += f.y * ex1;
        f = unpack_h2(w.y); acc[2] += f.x * ex1; acc[3] += f.y * ex1;
        f = unpack_h2(w.z); acc[4] += f.x * ex1; acc[5] += f.y * ex1;
        f = unpack_h2(w.w); acc[6] += f.x * ex1; acc[7] += f.y * ex1;
    }
    if (k < end) {
        int s = __ldg(&csr_src[k]);
        float ex = __expf(lrelu(__ldg(&as[s * 4 + head]) + advh));
        den += ex;
        uint4 u = ((const uint4*)(h16 + (size_t)s * 256))[lane];
        float2 f;
        f = unpack_h2(u.x); acc[0] += f.x * ex; acc[1] += f.y * ex;
        f = unpack_h2(u.y); acc[2] += f.x * ex; acc[3] += f.y * ex;
        f = unpack_h2(u.z); acc[4] += f.x * ex; acc[5] += f.y * ex;
        f = unpack_h2(u.w); acc[6] += f.x * ex; acc[7] += f.y * ex;
    }
    float inv = 1.0f / (den + EPS);
    const float* bp = bias + lane * 8;
    float4 o0, o1;
    o0.x = fmaxf(acc[0] * inv + bp[0], 0.f); o0.y = fmaxf(acc[1] * inv + bp[1], 0.f);
    o0.z = fmaxf(acc[2] * inv + bp[2], 0.f); o0.w = fmaxf(acc[3] * inv + bp[3], 0.f);
    o1.x = fmaxf(acc[4] * inv + bp[4], 0.f); o1.y = fmaxf(acc[5] * inv + bp[5], 0.f);
    o1.z = fmaxf(acc[6] * inv + bp[6], 0.f); o1.w = fmaxf(acc[7] * inv + bp[7], 0.f);
    float4* orow = (float4*)(out + (size_t)node * 256) + lane * 2;
    orow[0] = o0;
    orow[1] = o1;
}

__global__ void gat_node1_pool(const __half* __restrict__ h16, const float* __restrict__ as,
                               const float* __restrict__ ad, const int* __restrict__ off,
                               const int* __restrict__ csr_src,
                               const float* __restrict__ bias, const int* __restrict__ batch,
                               float* __restrict__ pool) {
    int node = (blockIdx.x * blockDim.x + threadIdx.x) >> 5;
    int lane = threadIdx.x & 31;
    if (node >= N_NODES) return;
    int start = off[node], end = off[node + 1];
    float adv = ad[node];

    float acc0 = 0.f, acc1 = 0.f, den = 0.f;
    int k = start;
    for (; k + 2 <= end; k += 2) {
        int s0 = __ldg(&csr_src[k]);
        int s1 = __ldg(&csr_src[k + 1]);
        float a0 = __ldg(&as[s0]);
        float a1 = __ldg(&as[s1]);
        uint32_t u0 = ((const uint32_t*)(h16 + (size_t)s0 * 64))[lane];
        uint32_t u1 = ((const uint32_t*)(h16 + (size_t)s1 * 64))[lane];
        float ex0 = __expf(lrelu(a0 + adv));
        float ex1 = __expf(lrelu(a1 + adv));
        den += ex0 + ex1;
        float2 v0 = unpack_h2(u0);
        float2 v1 = unpack_h2(u1);
        acc0 += v0.x * ex0 + v1.x * ex1;
        acc1 += v0.y * ex0 + v1.y * ex1;
    }
    if (k < end) {
        int s = __ldg(&csr_src[k]);
        float ex = __expf(lrelu(__ldg(&as[s]) + adv));
        den += ex;
        float2 v = unpack_h2(((const uint32_t*)(h16 + (size_t)s * 64))[lane]);
        acc0 += v.x * ex;
        acc1 += v.y * ex;
    }
    float inv = 1.0f / (den + EPS);
    float o0 = fmaxf(acc0 * inv + bias[lane * 2], 0.f);
    float o1 = fmaxf(acc1 * inv + bias[lane * 2 + 1], 0.f);
    int g = batch[node];
    red_add_v2(pool + g * 64 + lane * 2, o0, o1);
    if (lane == 0) atomicAdd(&pool[NG * 64 + g], 1.0f);
}

// ---------------- classifier -----------------------------------------------------
__global__ void classifier(const float* __restrict__ pool, const float* __restrict__ Wl,
                           const float* __restrict__ bl, float* __restrict__ out) {
    int t = threadIdx.x;
    if (t >= NG * NCLS) return;
    int g = t / NCLS, j = t % NCLS;
    float cnt = fmaxf(pool[NG * 64 + g], 1.0f);
    float s = 0.0f;
#pragma unroll
    for (int c = 0; c < 64; c++) s += pool[g * 64 + c] * Wl[c * NCLS + j];
    out[t] = s / cnt + bl[j];
}

// ---------------- launch --------------------------------------------------------
extern "C" void kernel_launch(void* const* d_in, const int* in_sizes, int n_in,
                              void* d_out, int out_size) {
    const float* x   = (const float*)d_in[0];
    const void*  ei  = d_in[1];
    const void*  bat = d_in[2];
    const float* W1 = (const float*)d_in[3];
    const float* s1 = (const float*)d_in[4];
    const float* t1 = (const float*)d_in[5];
    const float* b1 = (const float*)d_in[6];
    const float* W2 = (const float*)d_in[7];
    const float* s2w = (const float*)d_in[8];
    const float* t2 = (const float*)d_in[9];
    const float* b2 = (const float*)d_in[10];
    const float* W3 = (const float*)d_in[11];
    const float* s3 = (const float*)d_in[12];
    const float* t3 = (const float*)d_in[13];
    const float* b3 = (const float*)d_in[14];
    const float* Wl = (const float*)d_in[15];
    const float* bl = (const float*)d_in[16];
    float* out = (float*)d_out;

    float *B, *AS1, *AD1, *AS2, *AD2, *AS3, *AD3, *POOL;
    __half* H16;
    int *BATCH, *DEG, *INCL, *BSUM, *OFF, *CUR, *CSR;
    cudaGetSymbolAddress((void**)&B, g_bufB);
    cudaGetSymbolAddress((void**)&H16, g_h16);
    cudaGetSymbolAddress((void**)&AS1, g_as1);
    cudaGetSymbolAddress((void**)&AD1, g_ad1);
    cudaGetSymbolAddress((void**)&AS2, g_as2);
    cudaGetSymbolAddress((void**)&AD2, g_ad2);
    cudaGetSymbolAddress((void**)&AS3, g_as3);
    cudaGetSymbolAddress((void**)&AD3, g_ad3);
    cudaGetSymbolAddress((void**)&POOL, g_pool);
    cudaGetSymbolAddress((void**)&BATCH, g_batch);
    cudaGetSymbolAddress((void**)&DEG, g_deg);
    cudaGetSymbolAddress((void**)&INCL, g_incl);
    cudaGetSymbolAddress((void**)&BSUM, g_bsum);
    cudaGetSymbolAddress((void**)&OFF, g_off);
    cudaGetSymbolAddress((void**)&CUR, g_cursor);
    cudaGetSymbolAddress((void**)&CSR, g_csr_src);

    // lazily-created side stream + events (created on first, non-capture call)
    static cudaStream_t sCsr = nullptr;
    static cudaEvent_t evFork = nullptr, evJoin = nullptr;
    if (sCsr == nullptr) {
        cudaStreamCreateWithFlags(&sCsr, cudaStreamNonBlocking);
        cudaEventCreateWithFlags(&evFork, cudaEventDisableTiming);
        cudaEventCreateWithFlags(&evJoin, cudaEventDisableTiming);
    }

    const int TB = 256;
    int eThr = (EE + TB - 1) / TB;
    int nThr = (N_NODES + TB - 1) / TB;
    int nWarp = (N_NODES * 32 + TB - 1) / TB;
    int mT128 = (N_NODES + 127) / 128;
    int zThr = (N_NODES * 4 + TB - 1) / TB;

    // main: zero everything both branches depend on
    zero_all<<<zThr, TB>>>(DEG, POOL, AS1, AD1, AS2, AD2, AS3, AD3);

    // fork: CSR chain concurrent with layer-1 GEMM
    cudaEventRecord(evFork, 0);
    cudaStreamWaitEvent(sCsr, evFork, 0);
    prep2<<<eThr, TB, 0, sCsr>>>(ei, bat, DEG, BATCH);
    scan1<<<NB_SCAN, 256, 0, sCsr>>>(DEG, INCL, BSUM);
    scan2<<<1, 256, 0, sCsr>>>(BSUM);
    scan3<<<nThr, TB, 0, sCsr>>>(DEG, INCL, BSUM, OFF, CUR);
    scatter_csr<<<eThr, TB, 0, sCsr>>>(ei, CUR, CSR);
    cudaEventRecord(evJoin, sCsr);

    // main: layer-1 GEMM (independent of CSR)
    mma_gemm_fused<128><<<dim3(2, mT128), TB>>>(x, W1, s1, t1, AS1, AD1, H16,
                                                N_NODES, 256, 128);
    // join before first CSR consumer
    cudaStreamWaitEvent(0, evJoin, 0);
    gat_node4<<<nWarp, TB>>>(H16, AS1, AD1, OFF, CSR, b1, B);

    // ---- layer 2 ----
    mma_gemm_fused<128><<<dim3(2, mT128), TB>>>(B, W2, s2w, t2, AS2, AD2, H16,
                                                N_NODES, 256, 256);
    gat_node4<<<nWarp, TB>>>(H16, AS2, AD2, OFF, CSR, b2, B);

    // ---- layer 3 (heads=1, fused with pooling) ----
    mma_gemm_fused<64><<<dim3(1, mT128), TB>>>(B, W3, s3, t3, AS3, AD3, H16,
                                               N_NODES, 64, 256);
    gat_node1_pool<<<nWarp, TB>>>(H16, AS3, AD3, OFF, CSR, b3, BATCH, POOL);

    classifier<<<1, 640>>>(POOL, Wl, bl, out);
}

// round 17
// speedup vs baseline: 1.0720x; 1.0720x over previous
#include <cuda_runtime.h>
#include <cuda_fp16.h>
#include <cstdint>

#define N_NODES 50000
#define N_EDGES 800000
#define EE (N_EDGES + N_NODES)   // edges + self loops = 850000
#define NG 64
#define NCLS 10
#define NEG_SLOPE 0.2f
#define EPS 1e-16f
#define NB_SCAN ((N_NODES + 255) / 256)

// ---------------- scratch (static device globals; no runtime alloc) -------------
__device__ __align__(16) float  g_bufB[N_NODES * 256];  // gat output / next gemm input
__device__ __align__(16) __half g_h16[N_NODES * 256];   // fp16 h (written by gemm epilogue)
__device__ __align__(16) float  g_as1[N_NODES * 4];
__device__ __align__(16) float  g_ad1[N_NODES * 4];
__device__ __align__(16) float  g_as2[N_NODES * 4];
__device__ __align__(16) float  g_ad2[N_NODES * 4];
__device__ __align__(16) float  g_as3[N_NODES];
__device__ __align__(16) float  g_ad3[N_NODES];
__device__ __align__(16) int    g_batch[N_NODES];
__device__ __align__(16) int    g_deg[N_NODES];
__device__ __align__(16) int    g_incl[N_NODES];
__device__ __align__(16) int    g_bsum[256];
__device__ __align__(16) int    g_off[N_NODES + 1];
__device__ __align__(16) int    g_cursor[N_NODES];
__device__ __align__(16) int    g_csr_src[EE];
__device__ __align__(16) float  g_pool[NG * 64 + NG];

// ---------------- helpers -------------------------------------------------------
__device__ __forceinline__ void red_add_v2(float* addr, float a, float b) {
    asm volatile("red.global.add.v2.f32 [%0], {%1,%2};"
                 :: "l"(addr), "f"(a), "f"(b) : "memory");
}
__device__ __forceinline__ float lrelu(float v) { return v >= 0.0f ? v : NEG_SLOPE * v; }

__device__ __forceinline__ float f2tf32(float x) {
    uint32_t r;
    asm("cvt.rna.tf32.f32 %0, %1;" : "=r"(r) : "f"(x));
    return __uint_as_float(r);
}

__device__ __forceinline__ void mma_tf32(float* d, uint32_t a0, uint32_t a1,
                                         uint32_t a2, uint32_t a3,
                                         uint32_t b0, uint32_t b1) {
    asm("mma.sync.aligned.m16n8k8.row.col.f32.tf32.tf32.f32 "
        "{%0,%1,%2,%3},{%4,%5,%6,%7},{%8,%9},{%0,%1,%2,%3};"
        : "+f"(d[0]), "+f"(d[1]), "+f"(d[2]), "+f"(d[3])
        : "r"(a0), "r"(a1), "r"(a2), "r"(a3), "r"(b0), "r"(b1));
}

__device__ __forceinline__ uint32_t pack_h2(float a, float b) {
    __half2 h = __floats2half2_rn(a, b);
    return *(uint32_t*)&h;
}
__device__ __forceinline__ float2 unpack_h2(uint32_t u) {
    return __half22float2(*(__half2*)&u);
}

// edge-index dtype detect (shared-per-block). JAX may hand us int32 despite the
// reference requesting int64; fused ints read as int64 are wildly out of range.
__device__ __forceinline__ int detect_ei(const void* ei) {
    const long long* e64 = (const long long*)ei;
    int ok = 1;
    for (int j = 0; j < 8; j++) {
        long long v = e64[j];
        if (v < 0 || v >= N_NODES) ok = 0;
    }
    return ok;
}

// ---------------- zero_all: deg + pool + all as/ad buffers ----------------------
__global__ void zero_all(int* __restrict__ deg, float* __restrict__ pool,
                         float* __restrict__ as1, float* __restrict__ ad1,
                         float* __restrict__ as2, float* __restrict__ ad2,
                         float* __restrict__ as3, float* __restrict__ ad3) {
    int i = blockIdx.x * blockDim.x + threadIdx.x;
    if (i < N_NODES * 4) { as1[i] = 0.f; ad1[i] = 0.f; as2[i] = 0.f; ad2[i] = 0.f; }
    if (i < N_NODES)     { as3[i] = 0.f; ad3[i] = 0.f; deg[i] = 0; }
    if (i < NG * 64 + NG) pool[i] = 0.f;
}

// ---------------- prep2: dtype detect + degree hist + batch convert -------------
__global__ void prep2(const void* ei, const void* bat, int* __restrict__ deg,
                      int* __restrict__ batch) {
    __shared__ int f_e, f_b;
    if (threadIdx.x == 0) {
        f_e = detect_ei(ei);
        const long long* b64 = (const long long*)bat;
        int okb = 1;
        for (int j = 0; j < 8; j++) {
            long long v = b64[N_NODES / 2 - 1 - j];
            if (v < 0 || v >= NG) okb = 0;
        }
        f_b = okb;
    }
    __syncthreads();
    int i = blockIdx.x * blockDim.x + threadIdx.x;
    if (i < EE) {
        int d;
        if (i < N_EDGES) {
            if (f_e) d = (int)((const long long*)ei)[N_EDGES + i];
            else     d = ((const int*)ei)[N_EDGES + i];
        } else {
            d = i - N_EDGES;
        }
        atomicAdd(&deg[d], 1);
    }
    if (i < N_NODES) {
        if (f_b) batch[i] = (int)((const long long*)bat)[i];
        else     batch[i] = ((const int*)bat)[i];
    }
}

// ---------------- CSR scan (multi-block) ----------------------------------------
__global__ void scan1(const int* __restrict__ deg, int* __restrict__ incl,
                      int* __restrict__ bsum) {
    __shared__ int s[256];
    int t = threadIdx.x;
    int i = blockIdx.x * 256 + t;
    int v = (i < N_NODES) ? deg[i] : 0;
    s[t] = v;
    __syncthreads();
#pragma unroll
    for (int o = 1; o < 256; o <<= 1) {
        int x = (t >= o) ? s[t - o] : 0;
        __syncthreads();
        s[t] += x;
        __syncthreads();
    }
    if (i < N_NODES) incl[i] = s[t];
    if (t == 255) bsum[blockIdx.x] = s[255];
}

__global__ void scan2(int* __restrict__ bsum) {
    __shared__ int s[256];
    int t = threadIdx.x;
    int v = (t < NB_SCAN) ? bsum[t] : 0;
    s[t] = v;
    __syncthreads();
#pragma unroll
    for (int o = 1; o < 256; o <<= 1) {
        int x = (t >= o) ? s[t - o] : 0;
        __syncthreads();
        s[t] += x;
        __syncthreads();
    }
    bsum[t] = s[t] - v;
}

__global__ void scan3(const int* __restrict__ deg, const int* __restrict__ incl,
                      const int* __restrict__ bsum, int* __restrict__ off,
                      int* __restrict__ cursor) {
    int i = blockIdx.x * blockDim.x + threadIdx.x;
    if (i >= N_NODES) return;
    int o = incl[i] - deg[i] + bsum[i >> 8];
    off[i] = o;
    cursor[i] = o;
    if (i == 0) off[N_NODES] = EE;
}

// scatter reads edge_index directly (no src/dst intermediates)
__global__ void scatter_csr(const void* ei, int* __restrict__ cursor,
                            int* __restrict__ csr_src) {
    __shared__ int f_e;
    if (threadIdx.x == 0) f_e = detect_ei(ei);
    __syncthreads();
    int i = blockIdx.x * blockDim.x + threadIdx.x;
    if (i >= EE) return;
    int s, d;
    if (i < N_EDGES) {
        if (f_e) {
            const long long* e = (const long long*)ei;
            s = (int)e[i];
            d = (int)e[N_EDGES + i];
        } else {
            const int* e = (const int*)ei;
            s = e[i];
            d = e[N_EDGES + i];
        }
    } else {
        s = d = i - N_EDGES;
    }
    int pos = atomicAdd(&cursor[d], 1);
    csr_src[pos] = s;
}

// ---------------- TF32 GEMM (BK=16) with fused dots + fp16 emit epilogue ---------
// BK=16 with ~17.4KB SMEM/block keeps multiple blocks co-resident per SM; that
// co-residency is what covers the global-load latency (BK=32 halved it: -25us).
template <int BN>
__global__ void __launch_bounds__(256)
mma_gemm_fused(const float* __restrict__ A, const float* __restrict__ Bm,
               const float* __restrict__ a_src, const float* __restrict__ a_dst,
               float* __restrict__ as, float* __restrict__ ad,
               __half* __restrict__ h16, int M, int N, int K) {
    constexpr int WN = BN / 4;
    constexpr int NT = WN / 8;
    constexpr int NBL = (BN == 128) ? 2 : 1;
    __shared__ float As[16][136];
    __shared__ float Bs[16][BN + 8];
    int tid = threadIdx.x;
    int lane = tid & 31, warp = tid >> 5;
    int wm = (warp & 1) * 64, wn = (warp >> 1) * WN;
    int m0 = blockIdx.y * 128, n0 = blockIdx.x * BN;
    int l3 = lane & 3, l2 = lane >> 2;

    int arow[2], ac4[2];
#pragma unroll
    for (int i = 0; i < 2; i++) {
        int f = tid * 2 + i;
        arow[i] = f >> 2;
        ac4[i] = (f & 3) << 2;
    }
    int brow[2], bc4[2];
    if (BN == 128) {
#pragma unroll
        for (int i = 0; i < 2; i++) {
            int f = tid * 2 + i;
            brow[i] = f >> 5;
            bc4[i] = (f & 31) << 2;
        }
    } else {
        brow[0] = tid >> 4;
        bc4[0] = (tid & 15) << 2;
    }

    float4 avR[2], bvR[NBL];
#pragma unroll
    for (int i = 0; i < 2; i++) {
        avR[i] = make_float4(0.f, 0.f, 0.f, 0.f);
        if (m0 + arow[i] < M)
            avR[i] = *(const float4*)(A + (size_t)(m0 + arow[i]) * K + ac4[i]);
    }
#pragma unroll
    for (int i = 0; i < NBL; i++)
        bvR[i] = *(const float4*)(Bm + (size_t)brow[i] * N + n0 + bc4[i]);

    float acc[4][NT][4] = {};

    for (int k0 = 0; k0 < K; k0 += 16) {
#pragma unroll
        for (int i = 0; i < 2; i++) {
            As[ac4[i] + 0][arow[i]] = f2tf32(avR[i].x);
            As[ac4[i] + 1][arow[i]] = f2tf32(avR[i].y);
            As[ac4[i] + 2][arow[i]] = f2tf32(avR[i].z);
            As[ac4[i] + 3][arow[i]] = f2tf32(avR[i].w);
        }
#pragma unroll
        for (int i = 0; i < NBL; i++) {
            Bs[brow[i]][bc4[i] + 0] = f2tf32(bvR[i].x);
            Bs[brow[i]][bc4[i] + 1] = f2tf32(bvR[i].y);
            Bs[brow[i]][bc4[i] + 2] = f2tf32(bvR[i].z);
            Bs[brow[i]][bc4[i] + 3] = f2tf32(bvR[i].w);
        }
        __syncthreads();

        int k1 = k0 + 16;
        if (k1 < K) {
#pragma unroll
            for (int i = 0; i < 2; i++) {
                avR[i] = make_float4(0.f, 0.f, 0.f, 0.f);
                if (m0 + arow[i] < M)
                    avR[i] = *(const float4*)(A + (size_t)(m0 + arow[i]) * K + k1 + ac4[i]);
            }
#pragma unroll
            for (int i = 0; i < NBL; i++)
                bvR[i] = *(const float4*)(Bm + (size_t)(k1 + brow[i]) * N + n0 + bc4[i]);
        }

#pragma unroll
        for (int kk = 0; kk < 16; kk += 8) {
            uint32_t bf[NT][2];
#pragma unroll
            for (int j = 0; j < NT; j++) {
                bf[j][0] = __float_as_uint(Bs[kk + l3][wn + j * 8 + l2]);
                bf[j][1] = __float_as_uint(Bs[kk + l3 + 4][wn + j * 8 + l2]);
            }
#pragma unroll
            for (int i = 0; i < 4; i++) {
                uint32_t a0 = __float_as_uint(As[kk + l3][wm + i * 16 + l2]);
                uint32_t a1 = __float_as_uint(As[kk + l3][wm + i * 16 + l2 + 8]);
                uint32_t a2 = __float_as_uint(As[kk + l3 + 4][wm + i * 16 + l2]);
                uint32_t a3 = __float_as_uint(As[kk + l3 + 4][wm + i * 16 + l2 + 8]);
#pragma unroll
                for (int j = 0; j < NT; j++)
                    mma_tf32(acc[i][j], a0, a1, a2, a3, bf[j][0], bf[j][1]);
            }
        }
        __syncthreads();
    }

    // ---- fused epilogue: h16 emit + per-head attention dot partials ----
    int H = N >> 6;
    int head = (n0 + wn) >> 6;
    float asv[2 * NT], adv[2 * NT];
#pragma unroll
    for (int j = 0; j < NT; j++) {
        int cc = (n0 + wn + j * 8 + 2 * l3) & 63;
        asv[2 * j]     = a_src[head * 64 + cc];
        asv[2 * j + 1] = a_src[head * 64 + cc + 1];
        adv[2 * j]     = a_dst[head * 64 + cc];
        adv[2 * j + 1] = a_dst[head * 64 + cc + 1];
    }
#pragma unroll
    for (int i = 0; i < 4; i++) {
        int r0 = m0 + wm + i * 16 + l2;
        int r1 = r0 + 8;
        float ps0 = 0.f, pd0 = 0.f, ps1 = 0.f, pd1 = 0.f;
#pragma unroll
        for (int j = 0; j < NT; j++) {
            int c = n0 + wn + j * 8 + 2 * l3;
            ps0 += acc[i][j][0] * asv[2 * j] + acc[i][j][1] * asv[2 * j + 1];
            pd0 += acc[i][j][0] * adv[2 * j] + acc[i][j][1] * adv[2 * j + 1];
            ps1 += acc[i][j][2] * asv[2 * j] + acc[i][j][3] * asv[2 * j + 1];
            pd1 += acc[i][j][2] * adv[2 * j] + acc[i][j][3] * adv[2 * j + 1];
            if (r0 < M)
                ((uint32_t*)(h16 + (size_t)r0 * N))[c >> 1] = pack_h2(acc[i][j][0], acc[i][j][1]);
            if (r1 < M)
                ((uint32_t*)(h16 + (size_t)r1 * N))[c >> 1] = pack_h2(acc[i][j][2], acc[i][j][3]);
        }
        ps0 += __shfl_xor_sync(0xffffffffu, ps0, 1);
        ps0 += __shfl_xor_sync(0xffffffffu, ps0, 2);
        pd0 += __shfl_xor_sync(0xffffffffu, pd0, 1);
        pd0 += __shfl_xor_sync(0xffffffffu, pd0, 2);
        ps1 += __shfl_xor_sync(0xffffffffu, ps1, 1);
        ps1 += __shfl_xor_sync(0xffffffffu, ps1, 2);
        pd1 += __shfl_xor_sync(0xffffffffu, pd1, 1);
        pd1 += __shfl_xor_sync(0xffffffffu, pd1, 2);
        if (l3 == 0) {
            if (r0 < M) {
                atomicAdd(&as[r0 * H + head], ps0);
                atomicAdd(&ad[r0 * H + head], pd0);
            }
            if (r1 < M) {
                atomicAdd(&as[r1 * H + head], ps1);
                atomicAdd(&ad[r1 * H + head], pd1);
            }
        }
    }
}

// ---------------- fused GAT layer (softmax + aggregate + bias + relu) -----------
// Max-subtraction removed (softmax shift-invariant; e is O(+-1), no overflow).
__global__ void gat_node4(const __half* __restrict__ h16, const float* __restrict__ as,
                          const float* __restrict__ ad, const int* __restrict__ off,
                          const int* __restrict__ csr_src,
                          const float* __restrict__ bias, float* __restrict__ out) {
    int node = (blockIdx.x * blockDim.x + threadIdx.x) >> 5;
    int lane = threadIdx.x & 31;
    if (node >= N_NODES) return;
    int start = off[node], end = off[node + 1];
    float4 adv = ((const float4*)ad)[node];

    int head = lane >> 3;
    float advh = head == 0 ? adv.x : head == 1 ? adv.y : head == 2 ? adv.z : adv.w;
    float acc[8] = {};
    float den = 0.0f;
    int k = start;
    for (; k + 2 <= end; k += 2) {
        int s0 = __ldg(&csr_src[k]);
        int s1 = __ldg(&csr_src[k + 1]);
        float as0 = __ldg(&as[s0 * 4 + head]);
        float as1 = __ldg(&as[s1 * 4 + head]);
        uint4 u = ((const uint4*)(h16 + (size_t)s0 * 256))[lane];
        uint4 w = ((const uint4*)(h16 + (size_t)s1 * 256))[lane];
        float ex0 = __expf(lrelu(as0 + advh));
        float ex1 = __expf(lrelu(as1 + advh));
        den += ex0 + ex1;
        float2 f;
        f = unpack_h2(u.x); acc[0] += f.x * ex0; acc[1] += f.y * ex0;
        f = unpack_h2(u.y); acc[2] += f.x * ex0; acc[3] += f.y * ex0;
        f = unpack_h2(u.z); acc[4] += f.x * ex0; acc[5] += f.y * ex0;
        f = unpack_h2(u.w); acc[6] += f.x * ex0; acc[7] += f.y * ex0;
        f = unpack_h2(w.x); acc[0] += f.x * ex1; acc[1] += f.y * ex1;
        f = unpack_h2(w.y); acc[2] += f.x * ex1; acc[3] += f.y * ex1;
        f = unpack_h2(w.z); acc[4] += f.x * ex1; acc[5] += f.y * ex1;
        f = unpack_h2(w.w); acc[6] += f.x * ex1; acc[7] += f.y * ex1;
    }
    if (k < end) {
        int s = __ldg(&csr_src[k]);
        float ex = __expf(lrelu(__ldg(&as[s * 4 + head]) + advh));
        den += ex;
        uint4 u = ((const uint4*)(h16 + (size_t)s * 256))[lane];
        float2 f;
        f = unpack_h2(u.x); acc[0] += f.x * ex; acc[1] += f.y * ex;
        f = unpack_h2(u.y); acc[2] += f.x * ex; acc[3] += f.y * ex;
        f = unpack_h2(u.z); acc[4] += f.x * ex; acc[5] += f.y * ex;
        f = unpack_h2(u.w); acc[6] += f.x * ex; acc[7] += f.y * ex;
    }
    float inv = 1.0f / (den + EPS);
    const float* bp = bias + lane * 8;
    float4 o0, o1;
    o0.x = fmaxf(acc[0] * inv + bp[0], 0.f); o0.y = fmaxf(acc[1] * inv + bp[1], 0.f);
    o0.z = fmaxf(acc[2] * inv + bp[2], 0.f); o0.w = fmaxf(acc[3] * inv + bp[3], 0.f);
    o1.x = fmaxf(acc[4] * inv + bp[4], 0.f); o1.y = fmaxf(acc[5] * inv + bp[5], 0.f);
    o1.z = fmaxf(acc[6] * inv + bp[6], 0.f); o1.w = fmaxf(acc[7] * inv + bp[7], 0.f);
    float4* orow = (float4*)(out + (size_t)node * 256) + lane * 2;
    orow[0] = o0;
    orow[1] = o1;
}

__global__ void gat_node1_pool(const __half* __restrict__ h16, const float* __restrict__ as,
                               const float* __restrict__ ad, const int* __restrict__ off,
                               const int* __restrict__ csr_src,
                               const float* __restrict__ bias, const int* __restrict__ batch,
                               float* __restrict__ pool) {
    int node = (blockIdx.x * blockDim.x + threadIdx.x) >> 5;
    int lane = threadIdx.x & 31;
    if (node >= N_NODES) return;
    int start = off[node], end = off[node + 1];
    float adv = ad[node];

    float acc0 = 0.f, acc1 = 0.f, den = 0.f;
    int k = start;
    for (; k + 2 <= end; k += 2) {
        int s0 = __ldg(&csr_src[k]);
        int s1 = __ldg(&csr_src[k + 1]);
        float a0 = __ldg(&as[s0]);
        float a1 = __ldg(&as[s1]);
        uint32_t u0 = ((const uint32_t*)(h16 + (size_t)s0 * 64))[lane];
        uint32_t u1 = ((const uint32_t*)(h16 + (size_t)s1 * 64))[lane];
        float ex0 = __expf(lrelu(a0 + adv));
        float ex1 = __expf(lrelu(a1 + adv));
        den += ex0 + ex1;
        float2 v0 = unpack_h2(u0);
        float2 v1 = unpack_h2(u1);
        acc0 += v0.x * ex0 + v1.x * ex1;
        acc1 += v0.y * ex0 + v1.y * ex1;
    }
    if (k < end) {
        int s = __ldg(&csr_src[k]);
        float ex = __expf(lrelu(__ldg(&as[s]) + adv));
        den += ex;
        float2 v = unpack_h2(((const uint32_t*)(h16 + (size_t)s * 64))[lane]);
        acc0 += v.x * ex;
        acc1 += v.y * ex;
    }
    float inv = 1.0f / (den + EPS);
    float o0 = fmaxf(acc0 * inv + bias[lane * 2], 0.f);
    float o1 = fmaxf(acc1 * inv + bias[lane * 2 + 1], 0.f);
    int g = batch[node];
    red_add_v2(pool + g * 64 + lane * 2, o0, o1);
    if (lane == 0) atomicAdd(&pool[NG * 64 + g], 1.0f);
}

// ---------------- classifier -----------------------------------------------------
__global__ void classifier(const float* __restrict__ pool, const float* __restrict__ Wl,
                           const float* __restrict__ bl, float* __restrict__ out) {
    int t = threadIdx.x;
    if (t >= NG * NCLS) return;
    int g = t / NCLS, j = t % NCLS;
    float cnt = fmaxf(pool[NG * 64 + g], 1.0f);
    float s = 0.0f;
#pragma unroll
    for (int c = 0; c < 64; c++) s += pool[g * 64 + c] * Wl[c * NCLS + j];
    out[t] = s / cnt + bl[j];
}

// ---------------- launch --------------------------------------------------------
extern "C" void kernel_launch(void* const* d_in, const int* in_sizes, int n_in,
                              void* d_out, int out_size) {
    const float* x   = (const float*)d_in[0];
    const void*  ei  = d_in[1];
    const void*  bat = d_in[2];
    const float* W1 = (const float*)d_in[3];
    const float* s1 = (const float*)d_in[4];
    const float* t1 = (const float*)d_in[5];
    const float* b1 = (const float*)d_in[6];
    const float* W2 = (const float*)d_in[7];
    const float* s2w = (const float*)d_in[8];
    const float* t2 = (const float*)d_in[9];
    const float* b2 = (const float*)d_in[10];
    const float* W3 = (const float*)d_in[11];
    const float* s3 = (const float*)d_in[12];
    const float* t3 = (const float*)d_in[13];
    const float* b3 = (const float*)d_in[14];
    const float* Wl = (const float*)d_in[15];
    const float* bl = (const float*)d_in[16];
    float* out = (float*)d_out;

    float *B, *AS1, *AD1, *AS2, *AD2, *AS3, *AD3, *POOL;
    __half* H16;
    int *BATCH, *DEG, *INCL, *BSUM, *OFF, *CUR, *CSR;
    cudaGetSymbolAddress((void**)&B, g_bufB);
    cudaGetSymbolAddress((void**)&H16, g_h16);
    cudaGetSymbolAddress((void**)&AS1, g_as1);
    cudaGetSymbolAddress((void**)&AD1, g_ad1);
    cudaGetSymbolAddress((void**)&AS2, g_as2);
    cudaGetSymbolAddress((void**)&AD2, g_ad2);
    cudaGetSymbolAddress((void**)&AS3, g_as3);
    cudaGetSymbolAddress((void**)&AD3, g_ad3);
    cudaGetSymbolAddress((void**)&POOL, g_pool);
    cudaGetSymbolAddress((void**)&BATCH, g_batch);
    cudaGetSymbolAddress((void**)&DEG, g_deg);
    cudaGetSymbolAddress((void**)&INCL, g_incl);
    cudaGetSymbolAddress((void**)&BSUM, g_bsum);
    cudaGetSymbolAddress((void**)&OFF, g_off);
    cudaGetSymbolAddress((void**)&CUR, g_cursor);
    cudaGetSymbolAddress((void**)&CSR, g_csr_src);

    // lazily-created side stream + events (created on first, non-capture call)
    static cudaStream_t sCsr = nullptr;
    static cudaEvent_t evFork = nullptr, evJoin = nullptr;
    if (sCsr == nullptr) {
        cudaStreamCreateWithFlags(&sCsr, cudaStreamNonBlocking);
        cudaEventCreateWithFlags(&evFork, cudaEventDisableTiming);
        cudaEventCreateWithFlags(&evJoin, cudaEventDisableTiming);
    }

    const int TB = 256;
    int eThr = (EE + TB - 1) / TB;
    int nThr = (N_NODES + TB - 1) / TB;
    int nWarp = (N_NODES * 32 + TB - 1) / TB;
    int mT128 = (N_NODES + 127) / 128;
    int zThr = (N_NODES * 4 + TB - 1) / TB;

    // main: zero everything both branches depend on
    zero_all<<<zThr, TB>>>(DEG, POOL, AS1, AD1, AS2, AD2, AS3, AD3);

    // fork: CSR chain concurrent with layer-1 GEMM
    cudaEventRecord(evFork, 0);
    cudaStreamWaitEvent(sCsr, evFork, 0);
    prep2<<<eThr, TB, 0, sCsr>>>(ei, bat, DEG, BATCH);
    scan1<<<NB_SCAN, 256, 0, sCsr>>>(DEG, INCL, BSUM);
    scan2<<<1, 256, 0, sCsr>>>(BSUM);
    scan3<<<nThr, TB, 0, sCsr>>>(DEG, INCL, BSUM, OFF, CUR);
    scatter_csr<<<eThr, TB, 0, sCsr>>>(ei, CUR, CSR);
    cudaEventRecord(evJoin, sCsr);

    // main: layer-1 GEMM (independent of CSR)
    mma_gemm_fused<128><<<dim3(2, mT128), TB>>>(x, W1, s1, t1, AS1, AD1, H16,
                                                N_NODES, 256, 128);
    // join before first CSR consumer
    cudaStreamWaitEvent(0, evJoin, 0);
    gat_node4<<<nWarp, TB>>>(H16, AS1, AD1, OFF, CSR, b1, B);

    // ---- layer 2 ----
    mma_gemm_fused<128><<<dim3(2, mT128), TB>>>(B, W2, s2w, t2, AS2, AD2, H16,
                                                N_NODES, 256, 256);
    gat_node4<<<nWarp, TB>>>(H16, AS2, AD2, OFF, CSR, b2, B);

    // ---- layer 3 (heads=1, fused with pooling) ----
    mma_gemm_fused<64><<<dim3(1, mT128), TB>>>(B, W3, s3, t3, AS3, AD3, H16,
                                               N_NODES, 64, 256);
    gat_node1_pool<<<nWarp, TB>>>(H16, AS3, AD3, OFF, CSR, b3, BATCH, POOL);

    classifier<<<1, 640>>>(POOL, Wl, bl, out);
}